// round 15
// baseline (speedup 1.0000x reference)
#include <cuda_runtime.h>
#include <cstdint>

// Problem constants
#define BSZ   16
#define NDIM  256
#define DDIM  64
#define MCOLS (NDIM * DDIM)      // 16384
#define ABATCH (NDIM * NDIM)     // 65536
#define BBATCH (NDIM * MCOLS)    // 4194304

// GEMM tiling: block 128x128, 8 warps of 64x32, fp16 MMA m16n8k16, all-f16 smem
#define BM 128
#define BN 128
#define BK 32
#define ASTRH 40    // f16 per A row (80B = 5*16 odd -> ldmatrix conflict-free)
#define BSTRH 136   // f16 per B row (272B = 17*16 odd -> ldmatrix.trans conflict-free)
#define A_ST_B (BM * ASTRH * 2)   // 10240 B
#define B_ST_B (BK * BSTRH * 2)   // 8704 B
#define SMEM_BYTES (2 * (A_ST_B + B_ST_B))   // 37888 B

#define NB_CONVB ((BSZ * BBATCH / 8) / 256)   // 32768
#define NB_CONVA ((BSZ * ABATCH / 8) / 256)   // 512

__device__ uint16_t g_Ah[BSZ * ABATCH];    // 2 MB
__device__ uint16_t g_Bh[BSZ * BBATCH];    // 128 MB
__device__ int g_len[BSZ * 3];

// ---------------- mask helpers (dtype auto-detect) -------------------------
__device__ __forceinline__ bool mask_is_u8(const void* m) {
    return *(const unsigned int*)m == 0x01010101u;
}
__device__ __forceinline__ bool mask_at(const void* m, int idx, bool u8) {
    if (u8) return ((const unsigned char*)m)[idx] != 0;
    return ((const unsigned int*)m)[idx] != 0u;
}

__global__ void len_kernel(const void* __restrict__ Am,
                           const void* __restrict__ Bm,
                           const void* __restrict__ Tm) {
    int b = blockIdx.x;
    int tid = threadIdx.x;
    __shared__ int cnt[3];
    if (tid < 3) cnt[tid] = 0;
    __syncthreads();
    const void* base[3] = {Am, Bm, Tm};
    #pragma unroll
    for (int m = 0; m < 3; m++) {
        bool u8 = mask_is_u8(base[m]);
        int v = mask_at(base[m], b * ABATCH + tid, u8) ? 1 : 0;
        #pragma unroll
        for (int o = 16; o > 0; o >>= 1) v += __shfl_down_sync(0xffffffffu, v, o);
        if ((tid & 31) == 0) atomicAdd(&cnt[m], v);
    }
    __syncthreads();
    if (tid < 3) g_len[b * 3 + tid] = cnt[tid];
}

// ---------------------------------------------------------------------------
__device__ __forceinline__ uint32_t pack_h2(float lo, float hi) {
    uint32_t d;
    asm("cvt.rn.f16x2.f32 %0, %1, %2;" : "=r"(d) : "f"(hi), "f"(lo));
    return d;
}

// conv: blocks [0,NB_CONVB) convert live region of B; [NB_CONVB,+NB_CONVA) A.
__global__ void conv_kernel(const float* __restrict__ A,
                            const float* __restrict__ Bt) {
    if (blockIdx.x < NB_CONVB) {
        int c = blockIdx.x * 256 + threadIdx.x;      // 8-elem chunk id
        int b = c / (BBATCH / 8);
        int rem = c - b * (BBATCH / 8);
        int j = rem / (MCOLS / 8);
        int k = (rem % (MCOLS / 8)) >> 3;            // head index (8 chunks per head)
        int Kmin = min(g_len[b * 3], g_len[b * 3 + 1]);
        int Lk = min(g_len[b * 3 + 1], g_len[b * 3 + 2]);
        if (j >= Kmin || k >= Lk) return;            // dead region: skip
        const float4* src = reinterpret_cast<const float4*>(Bt) + c * 2;
        float4 v0 = src[0], v1 = src[1];
        uint4 o = make_uint4(pack_h2(v0.x, v0.y), pack_h2(v0.z, v0.w),
                             pack_h2(v1.x, v1.y), pack_h2(v1.z, v1.w));
        *(reinterpret_cast<uint4*>(g_Bh) + c) = o;
    } else {
        int c = (blockIdx.x - NB_CONVB) * 256 + threadIdx.x;
        const float4* src = reinterpret_cast<const float4*>(A) + c * 2;
        float4 v0 = src[0], v1 = src[1];
        uint4 o = make_uint4(pack_h2(v0.x, v0.y), pack_h2(v0.z, v0.w),
                             pack_h2(v1.x, v1.y), pack_h2(v1.z, v1.w));
        *(reinterpret_cast<uint4*>(g_Ah) + c) = o;
    }
}

// ---------------------------------------------------------------------------
__device__ __forceinline__ void cp_async16(uint32_t smem_addr, const void* gmem,
                                           int src_bytes) {
    asm volatile("cp.async.cg.shared.global [%0], [%1], 16, %2;\n"
                 :: "r"(smem_addr), "l"(gmem), "r"(src_bytes));
}
__device__ __forceinline__ uint32_t smem_u32(const void* p) {
    uint32_t a;
    asm("{ .reg .u64 t; cvta.to.shared.u64 t, %1; cvt.u32.u64 %0, t; }" : "=r"(a) : "l"(p));
    return a;
}
__device__ __forceinline__ void mma_f16(float* c, uint32_t a0, uint32_t a1,
                                        uint32_t a2, uint32_t a3,
                                        uint32_t b0, uint32_t b1) {
    asm volatile(
        "mma.sync.aligned.m16n8k16.row.col.f32.f16.f16.f32 "
        "{%0,%1,%2,%3}, {%4,%5,%6,%7}, {%8,%9}, {%0,%1,%2,%3};"
        : "+f"(c[0]), "+f"(c[1]), "+f"(c[2]), "+f"(c[3])
        : "r"(a0), "r"(a1), "r"(a2), "r"(a3), "r"(b0), "r"(b1));
}
__device__ __forceinline__ void ldmatrix_x4(uint32_t* r, uint32_t addr) {
    asm volatile("ldmatrix.sync.aligned.m8n8.x4.shared.b16 {%0,%1,%2,%3}, [%4];"
                 : "=r"(r[0]), "=r"(r[1]), "=r"(r[2]), "=r"(r[3]) : "r"(addr));
}
__device__ __forceinline__ void ldmatrix_x4_t(uint32_t* r, uint32_t addr) {
    asm volatile("ldmatrix.sync.aligned.m8n8.x4.trans.shared.b16 {%0,%1,%2,%3}, [%4];"
                 : "=r"(r[0]), "=r"(r[1]), "=r"(r[2]), "=r"(r[3]) : "r"(addr));
}

__global__ __launch_bounds__(256, 2)
void gemm_kernel(const void* __restrict__ tar, float* __restrict__ C) {
    extern __shared__ char smem[];

    const int b  = blockIdx.z;
    const int m0 = blockIdx.x * BN;
    const int i0 = blockIdx.y * BM;
    const int tid = threadIdx.x;

    const int L1 = g_len[b * 3 + 0];
    const int L2 = g_len[b * 3 + 1];
    const int L3 = g_len[b * 3 + 2];

    float* Cb = C + (size_t)b * BBATCH;

    // ---- tile-level liveness ----
    const int Li = min(L1, L3);
    const int Lk = min(L2, L3);
    if (i0 >= Li || (m0 >> 6) >= Lk) {
        float4 z = make_float4(0.f, 0.f, 0.f, 0.f);
        #pragma unroll
        for (int q = 0; q < 16; q++) {
            int c = tid + q * 256;
            int row = i0 + (c >> 5);
            int col = m0 + (c & 31) * 4;
            *reinterpret_cast<float4*>(Cb + (size_t)row * MCOLS + col) = z;
        }
        return;
    }

    uint32_t as_base[2], bs_base[2];
    #pragma unroll
    for (int s = 0; s < 2; s++) {
        as_base[s] = smem_u32(smem + s * A_ST_B);
        bs_base[s] = smem_u32(smem + 2 * A_ST_B + s * B_ST_B);
    }

    const int lane = tid & 31;
    const int w = tid >> 5;
    const int wm = w >> 2;      // 0..1 -> 64 rows
    const int wn = w & 3;       // 0..3 -> 32 cols
    const int g = lane >> 2;    // 0..7
    const int r = lane & 3;     // 0..3

    const int Kmin = min(L1, L2);
    const int T = (Kmin + BK - 1) / BK;   // 4..8

    const uint16_t* Ab = g_Ah + b * ABATCH + i0 * NDIM;
    const uint16_t* Bb = g_Bh + (size_t)b * BBATCH + m0;

    float acc[4][4][4];
    #pragma unroll
    for (int mf = 0; mf < 4; mf++)
        #pragma unroll
        for (int nf = 0; nf < 4; nf++)
            #pragma unroll
            for (int q = 0; q < 4; q++) acc[mf][nf][q] = 0.0f;

    // producer coords (A: verified R12/R13; B: verified R9/R10)
    const int a_r0 = tid >> 2;       // rows tid>>2, +64
    const int a_c  = tid & 3;        // 8-f16 chunk
    const int b_k0 = tid >> 4;       // rows 0..15, +16
    const int b_c  = tid & 15;       // 8-f16 chunk (128 f16/row -> 16 chunks)

    auto issue = [&](int t, int s) {
        const int k0 = t * BK;
        {
            int kk = k0 + a_c * 8;
            int nb = 2 * (Kmin - kk);
            nb = nb < 0 ? 0 : (nb > 16 ? 16 : nb);
            #pragma unroll
            for (int q = 0; q < 2; q++) {
                int row = a_r0 + q * 64;
                cp_async16(as_base[s] + (row * ASTRH + a_c * 8) * 2,
                           Ab + row * NDIM + kk, nb);
            }
        }
        #pragma unroll
        for (int q = 0; q < 2; q++) {
            int kk = b_k0 + q * 16;
            int j = k0 + kk;
            cp_async16(bs_base[s] + (kk * BSTRH + b_c * 8) * 2,
                       Bb + (size_t)j * MCOLS + b_c * 8,
                       (j < Kmin) ? 16 : 0);
        }
        asm volatile("cp.async.commit_group;\n" ::: "memory");
    };

    // consumer addressing (A: verified R8; B: verified R9/R10)
    const int lm = lane & 15;
    const int lh = lane >> 4;
    const uint32_t a_off0 = ((wm * 64 + lm) * ASTRH + lh * 8) * 2;
    const uint32_t b_off0 = (lm * BSTRH + wn * 32 + lh * 8) * 2;

    issue(0, 0);

    for (int t = 0; t < T; t++) {
        const int s = t & 1;
        if (t + 1 < T) {
            issue(t + 1, s ^ 1);
            asm volatile("cp.async.wait_group 1;\n" ::: "memory");
        } else {
            asm volatile("cp.async.wait_group 0;\n" ::: "memory");
        }
        __syncthreads();

        #pragma unroll
        for (int ks = 0; ks < 2; ks++) {
            uint32_t af[4][4];
            uint32_t bf[2][4];
            #pragma unroll
            for (int mf = 0; mf < 4; mf++)
                ldmatrix_x4(af[mf], as_base[s] + a_off0
                            + (mf * 16 * ASTRH + ks * 16) * 2);
            #pragma unroll
            for (int pair = 0; pair < 2; pair++)
                ldmatrix_x4_t(bf[pair], bs_base[s] + b_off0
                              + (ks * 16 * BSTRH + pair * 16) * 2);
            #pragma unroll
            for (int mf = 0; mf < 4; mf++) {
                #pragma unroll
                for (int pair = 0; pair < 2; pair++) {
                    mma_f16(acc[mf][pair * 2],     af[mf][0], af[mf][1],
                            af[mf][2], af[mf][3], bf[pair][0], bf[pair][1]);
                    mma_f16(acc[mf][pair * 2 + 1], af[mf][0], af[mf][1],
                            af[mf][2], af[mf][3], bf[pair][2], bf[pair][3]);
                }
            }
        }
        __syncthreads();
    }

    // ---- epilogue: warp covers 64 rows x 32 cols -> single kcol ----
    const bool u8 = mask_is_u8(tar);
    const int kcol = (m0 >> 6) + (wn >> 1);
    const bool vcol = (kcol < L2);

    bool rmask[4][2];
    #pragma unroll
    for (int mf = 0; mf < 4; mf++) {
        #pragma unroll
        for (int h = 0; h < 2; h++) {
            int i = i0 + wm * 64 + mf * 16 + g + h * 8;
            rmask[mf][h] = vcol && (i < L1)
                           && mask_at(tar, b * ABATCH + i * NDIM + kcol, u8);
        }
    }

    #pragma unroll
    for (int mf = 0; mf < 4; mf++) {
        int row = i0 + wm * 64 + mf * 16 + g;
        #pragma unroll
        for (int nf = 0; nf < 4; nf++) {
            int col = m0 + wn * 32 + nf * 8 + r * 2;
            float2 v0 = rmask[mf][0] ? make_float2(acc[mf][nf][0], acc[mf][nf][1])
                                     : make_float2(0.0f, 0.0f);
            float2 v1 = rmask[mf][1] ? make_float2(acc[mf][nf][2], acc[mf][nf][3])
                                     : make_float2(0.0f, 0.0f);
            *reinterpret_cast<float2*>(Cb + (size_t)row * MCOLS + col) = v0;
            *reinterpret_cast<float2*>(Cb + (size_t)(row + 8) * MCOLS + col) = v1;
        }
    }
}

// ---------------------------------------------------------------------------
extern "C" void kernel_launch(void* const* d_in, const int* in_sizes, int n_in,
                              void* d_out, int out_size) {
    (void)in_sizes; (void)n_in; (void)out_size;
    const float* A  = (const float*)d_in[0];
    const void*  Am = d_in[1];
    const float* Bt = (const float*)d_in[2];
    const void*  Bm = d_in[3];
    const void*  Tm = d_in[4];
    float* C = (float*)d_out;

    cudaFuncSetAttribute(gemm_kernel,
                         cudaFuncAttributeMaxDynamicSharedMemorySize, SMEM_BYTES);

    len_kernel<<<BSZ, 256>>>(Am, Bm, Tm);
    conv_kernel<<<NB_CONVB + NB_CONVA, 256>>>(A, Bt);

    dim3 grid(MCOLS / BN, NDIM / BM, BSZ);
    gemm_kernel<<<grid, 256, SMEM_BYTES>>>(Tm, C);
}

// round 16
// speedup vs baseline: 1.0113x; 1.0113x over previous
#include <cuda_runtime.h>
#include <cstdint>

// Problem constants
#define BSZ   16
#define NDIM  256
#define DDIM  64
#define MCOLS (NDIM * DDIM)      // 16384
#define ABATCH (NDIM * NDIM)     // 65536
#define BBATCH (NDIM * MCOLS)    // 4194304

// GEMM tiling: block 128x128, 8 warps of 64x32, fp16 MMA m16n8k16
// A: f16 smem (ldmatrix), B: f32 smem (pack in loop)
#define BM 128
#define BN 128
#define BK 32
#define STAGES 4
#define ASTRH 40    // f16 per A row (80B = 5*16 odd -> ldmatrix conflict-free)
#define BSTR 132    // f32 words per B row (+4 pad; frag banks 8r+g distinct)
#define A_ST_B (BM * ASTRH * 2)   // 10240 B
#define B_ST_B (BK * BSTR * 4)    // 16896 B
#define SMEM_BYTES (STAGES * (A_ST_B + B_ST_B))   // 108544 B

#define NB_CONVA ((BSZ * ABATCH / 8) / 256)   // 512

__device__ uint16_t g_Ah[BSZ * ABATCH];    // 2 MB f16 A
__device__ int g_len[BSZ * 3];

// ---------------- mask helpers (dtype auto-detect) -------------------------
__device__ __forceinline__ bool mask_is_u8(const void* m) {
    return *(const unsigned int*)m == 0x01010101u;
}
__device__ __forceinline__ bool mask_at(const void* m, int idx, bool u8) {
    if (u8) return ((const unsigned char*)m)[idx] != 0;
    return ((const unsigned int*)m)[idx] != 0u;
}

// ---------------------------------------------------------------------------
__device__ __forceinline__ uint32_t pack_h2(float lo, float hi) {
    uint32_t d;
    asm("cvt.rn.f16x2.f32 %0, %1, %2;" : "=r"(d) : "f"(hi), "f"(lo));
    return d;
}

// prep: blocks [0,NB_CONVA) convert A f32->f16; blocks [NB_CONVA, +BSZ) do len
__global__ void prep_kernel(const float* __restrict__ A,
                            const void* __restrict__ Am,
                            const void* __restrict__ Bm,
                            const void* __restrict__ Tm) {
    if (blockIdx.x < NB_CONVA) {
        int c = blockIdx.x * 256 + threadIdx.x;
        const float4* src = reinterpret_cast<const float4*>(A) + c * 2;
        float4 v0 = src[0], v1 = src[1];
        uint4 o = make_uint4(pack_h2(v0.x, v0.y), pack_h2(v0.z, v0.w),
                             pack_h2(v1.x, v1.y), pack_h2(v1.z, v1.w));
        *(reinterpret_cast<uint4*>(g_Ah) + c) = o;
    } else {
        int b = blockIdx.x - NB_CONVA;
        int tid = threadIdx.x;
        __shared__ int cnt[3];
        if (tid < 3) cnt[tid] = 0;
        __syncthreads();
        const void* base[3] = {Am, Bm, Tm};
        #pragma unroll
        for (int m = 0; m < 3; m++) {
            bool u8 = mask_is_u8(base[m]);
            int v = mask_at(base[m], b * ABATCH + tid, u8) ? 1 : 0;
            #pragma unroll
            for (int o = 16; o > 0; o >>= 1)
                v += __shfl_down_sync(0xffffffffu, v, o);
            if ((tid & 31) == 0) atomicAdd(&cnt[m], v);
        }
        __syncthreads();
        if (tid < 3) g_len[b * 3 + tid] = cnt[tid];
    }
}

// ---------------------------------------------------------------------------
__device__ __forceinline__ void cp_async16(uint32_t smem_addr, const void* gmem,
                                           int src_bytes) {
    asm volatile("cp.async.cg.shared.global [%0], [%1], 16, %2;\n"
                 :: "r"(smem_addr), "l"(gmem), "r"(src_bytes));
}
__device__ __forceinline__ uint32_t smem_u32(const void* p) {
    uint32_t a;
    asm("{ .reg .u64 t; cvta.to.shared.u64 t, %1; cvt.u32.u64 %0, t; }" : "=r"(a) : "l"(p));
    return a;
}
__device__ __forceinline__ void mma_f16(float* c, uint32_t a0, uint32_t a1,
                                        uint32_t a2, uint32_t a3,
                                        uint32_t b0, uint32_t b1) {
    asm volatile(
        "mma.sync.aligned.m16n8k16.row.col.f32.f16.f16.f32 "
        "{%0,%1,%2,%3}, {%4,%5,%6,%7}, {%8,%9}, {%0,%1,%2,%3};"
        : "+f"(c[0]), "+f"(c[1]), "+f"(c[2]), "+f"(c[3])
        : "r"(a0), "r"(a1), "r"(a2), "r"(a3), "r"(b0), "r"(b1));
}
__device__ __forceinline__ void ldmatrix_x4(uint32_t* r, uint32_t addr) {
    asm volatile("ldmatrix.sync.aligned.m8n8.x4.shared.b16 {%0,%1,%2,%3}, [%4];"
                 : "=r"(r[0]), "=r"(r[1]), "=r"(r[2]), "=r"(r[3]) : "r"(addr));
}

__global__ __launch_bounds__(256, 2)
void gemm_kernel(const float* __restrict__ Bt,
                 const void* __restrict__ tar,
                 float* __restrict__ C) {
    extern __shared__ char smem[];

    const int b  = blockIdx.z;
    const int m0 = blockIdx.x * BN;
    const int i0 = blockIdx.y * BM;
    const int tid = threadIdx.x;

    const int L1 = g_len[b * 3 + 0];
    const int L2 = g_len[b * 3 + 1];
    const int L3 = g_len[b * 3 + 2];

    float* Cb = C + (size_t)b * BBATCH;

    // ---- tile-level liveness: nonzero only for i<min(L1,L3), k<min(L2,L3) ----
    const int Li = min(L1, L3);
    const int Lk = min(L2, L3);
    if (i0 >= Li || (m0 >> 6) >= Lk) {
        float4 z = make_float4(0.f, 0.f, 0.f, 0.f);
        #pragma unroll
        for (int q = 0; q < 16; q++) {
            int c = tid + q * 256;
            int row = i0 + (c >> 5);
            int col = m0 + (c & 31) * 4;
            *reinterpret_cast<float4*>(Cb + (size_t)row * MCOLS + col) = z;
        }
        return;
    }

    uint32_t as_base[STAGES], bs_base[STAGES];
    float* Bsf[STAGES];
    #pragma unroll
    for (int s = 0; s < STAGES; s++) {
        as_base[s] = smem_u32(smem + s * A_ST_B);
        bs_base[s] = smem_u32(smem + STAGES * A_ST_B + s * B_ST_B);
        Bsf[s] = reinterpret_cast<float*>(smem + STAGES * A_ST_B + s * B_ST_B);
    }

    const int lane = tid & 31;
    const int w = tid >> 5;
    const int wm = w >> 2;      // 0..1 -> 64 rows
    const int wn = w & 3;       // 0..3 -> 32 cols
    const int g = lane >> 2;    // 0..7
    const int r = lane & 3;     // 0..3

    const int Kmin = min(L1, L2);
    const int T = (Kmin + BK - 1) / BK;   // 4..8

    const uint16_t* Ab = g_Ah + b * ABATCH + i0 * NDIM;
    const float* Bb = Bt + (size_t)b * BBATCH + m0;

    float acc[4][4][4];
    #pragma unroll
    for (int mf = 0; mf < 4; mf++)
        #pragma unroll
        for (int nf = 0; nf < 4; nf++)
            #pragma unroll
            for (int q = 0; q < 4; q++) acc[mf][nf][q] = 0.0f;

    // producer coords (verified R12-R14)
    const int a_r0 = tid >> 2;       // rows tid>>2, +64
    const int a_c  = tid & 3;        // 8-f16 chunk (32 f16/row -> 4 chunks)
    const int b_j0 = tid >> 5;       // rows 0..7, +8q
    const int b_c  = tid & 31;       // 4-f32 chunk (128 f32/row -> 32 chunks)

    auto issue = [&](int t, int s) {
        const int k0 = t * BK;
        {
            int kk = k0 + a_c * 8;
            int nb = 2 * (Kmin - kk);
            nb = nb < 0 ? 0 : (nb > 16 ? 16 : nb);
            #pragma unroll
            for (int q = 0; q < 2; q++) {
                int row = a_r0 + q * 64;
                cp_async16(as_base[s] + (row * ASTRH + a_c * 8) * 2,
                           Ab + row * NDIM + kk, nb);
            }
        }
        #pragma unroll
        for (int q = 0; q < 4; q++) {
            int jj = b_j0 + q * 8;
            int j = k0 + jj;
            cp_async16(bs_base[s] + (jj * BSTR + b_c * 4) * 4,
                       Bb + (size_t)j * MCOLS + b_c * 4,
                       (j < Kmin) ? 16 : 0);
        }
        asm volatile("cp.async.commit_group;\n" ::: "memory");
    };

    // consumer addressing (A: verified R8; B: verified R7)
    const int lm = lane & 15;
    const int lh = lane >> 4;
    const uint32_t a_off0 = ((wm * 64 + lm) * ASTRH + lh * 8) * 2;

    // prologue: 3 tiles in flight (T >= 4 always)
    issue(0, 0);
    issue(1, 1);
    issue(2, 2);

    for (int t = 0; t < T; t++) {
        const int s = t & (STAGES - 1);
        // complete group t: pending = min(3, T - t) -> wait (pending-1)
        if (t + 3 <= T) {
            asm volatile("cp.async.wait_group 2;\n" ::: "memory");
        } else if (t + 2 == T) {
            asm volatile("cp.async.wait_group 1;\n" ::: "memory");
        } else {
            asm volatile("cp.async.wait_group 0;\n" ::: "memory");
        }
        __syncthreads();   // all warps done with stage (t-1)%4; stage t visible

        const float* Bw = &Bsf[s][(2 * r) * BSTR + wn * 32 + g];

        #pragma unroll
        for (int ks = 0; ks < 2; ks++) {
            uint32_t af[4][4];
            uint32_t b0[4], b1[4];
            #pragma unroll
            for (int mf = 0; mf < 4; mf++)
                ldmatrix_x4(af[mf], as_base[s] + a_off0
                            + (mf * 16 * ASTRH + ks * 16) * 2);
            #pragma unroll
            for (int nf = 0; nf < 4; nf++) {
                const float* p = Bw + ks * 16 * BSTR + nf * 8;
                b0[nf] = pack_h2(p[0], p[BSTR]);
                b1[nf] = pack_h2(p[8 * BSTR], p[9 * BSTR]);
            }
            #pragma unroll
            for (int mf = 0; mf < 4; mf++)
                #pragma unroll
                for (int nf = 0; nf < 4; nf++)
                    mma_f16(acc[mf][nf], af[mf][0], af[mf][1],
                            af[mf][2], af[mf][3], b0[nf], b1[nf]);
        }

        // refill stage (t+3)%4 == (t-1)%4: all warps passed the barrier above,
        // so nobody is still reading it.
        if (t + 3 < T) issue(t + 3, (t + 3) & (STAGES - 1));
    }

    // ---- epilogue: warp covers 64 rows x 32 cols -> single kcol ----
    const bool u8 = mask_is_u8(tar);
    const int kcol = (m0 >> 6) + (wn >> 1);
    const bool vcol = (kcol < L2);

    bool rmask[4][2];
    #pragma unroll
    for (int mf = 0; mf < 4; mf++) {
        #pragma unroll
        for (int h = 0; h < 2; h++) {
            int i = i0 + wm * 64 + mf * 16 + g + h * 8;
            rmask[mf][h] = vcol && (i < L1)
                           && mask_at(tar, b * ABATCH + i * NDIM + kcol, u8);
        }
    }

    #pragma unroll
    for (int mf = 0; mf < 4; mf++) {
        int row = i0 + wm * 64 + mf * 16 + g;
        #pragma unroll
        for (int nf = 0; nf < 4; nf++) {
            int col = m0 + wn * 32 + nf * 8 + r * 2;
            float2 v0 = rmask[mf][0] ? make_float2(acc[mf][nf][0], acc[mf][nf][1])
                                     : make_float2(0.0f, 0.0f);
            float2 v1 = rmask[mf][1] ? make_float2(acc[mf][nf][2], acc[mf][nf][3])
                                     : make_float2(0.0f, 0.0f);
            *reinterpret_cast<float2*>(Cb + (size_t)row * MCOLS + col) = v0;
            *reinterpret_cast<float2*>(Cb + (size_t)(row + 8) * MCOLS + col) = v1;
        }
    }
}

// ---------------------------------------------------------------------------
extern "C" void kernel_launch(void* const* d_in, const int* in_sizes, int n_in,
                              void* d_out, int out_size) {
    (void)in_sizes; (void)n_in; (void)out_size;
    const float* A  = (const float*)d_in[0];
    const void*  Am = d_in[1];
    const float* Bt = (const float*)d_in[2];
    const void*  Bm = d_in[3];
    const void*  Tm = d_in[4];
    float* C = (float*)d_out;

    cudaFuncSetAttribute(gemm_kernel,
                         cudaFuncAttributeMaxDynamicSharedMemorySize, SMEM_BYTES);

    prep_kernel<<<NB_CONVA + BSZ, 256>>>(A, Am, Bm, Tm);

    dim3 grid(MCOLS / BN, NDIM / BM, BSZ);
    gemm_kernel<<<grid, 256, SMEM_BYTES>>>(Bt, Tm, C);
}

// round 17
// speedup vs baseline: 1.1108x; 1.0984x over previous
#include <cuda_runtime.h>
#include <cstdint>

// Problem constants
#define BSZ   16
#define NDIM  256
#define DDIM  64
#define MCOLS (NDIM * DDIM)      // 16384
#define ABATCH (NDIM * NDIM)     // 65536
#define BBATCH (NDIM * MCOLS)    // 4194304

// GEMM tiling: block 128(M)x64(N), 4 warps of 64x32, fp16 MMA m16n8k16
// A: f16 smem (ldmatrix), B: f32 smem (pack in loop). 4 CTAs/SM.
#define BM 128
#define BN 64
#define BK 32
#define THREADS 128
#define ASTRH 40    // f16 per A row (80B = 5*16 odd -> ldmatrix conflict-free)
#define BSTR 68     // f32 words per B row (272B; frag banks 8r+g distinct)
#define A_ST_B (BM * ASTRH * 2)   // 10240 B
#define B_ST_B (BK * BSTR * 4)    // 8704 B
#define SMEM_BYTES (2 * (A_ST_B + B_ST_B))   // 37888 B

#define NB_CONVA ((BSZ * ABATCH / 8) / 256)   // 512

__device__ uint16_t g_Ah[BSZ * ABATCH];    // 2 MB f16 A
__device__ int g_len[BSZ * 3];

// ---------------- mask helpers (dtype auto-detect) -------------------------
__device__ __forceinline__ bool mask_is_u8(const void* m) {
    return *(const unsigned int*)m == 0x01010101u;
}
__device__ __forceinline__ bool mask_at(const void* m, int idx, bool u8) {
    if (u8) return ((const unsigned char*)m)[idx] != 0;
    return ((const unsigned int*)m)[idx] != 0u;
}

// ---------------------------------------------------------------------------
__device__ __forceinline__ uint32_t pack_h2(float lo, float hi) {
    uint32_t d;
    asm("cvt.rn.f16x2.f32 %0, %1, %2;" : "=r"(d) : "f"(hi), "f"(lo));
    return d;
}

// prep: blocks [0,NB_CONVA) convert A f32->f16; blocks [NB_CONVA, +BSZ) do len
__global__ void prep_kernel(const float* __restrict__ A,
                            const void* __restrict__ Am,
                            const void* __restrict__ Bm,
                            const void* __restrict__ Tm) {
    if (blockIdx.x < NB_CONVA) {
        int c = blockIdx.x * 256 + threadIdx.x;
        const float4* src = reinterpret_cast<const float4*>(A) + c * 2;
        float4 v0 = src[0], v1 = src[1];
        uint4 o = make_uint4(pack_h2(v0.x, v0.y), pack_h2(v0.z, v0.w),
                             pack_h2(v1.x, v1.y), pack_h2(v1.z, v1.w));
        *(reinterpret_cast<uint4*>(g_Ah) + c) = o;
    } else {
        int b = blockIdx.x - NB_CONVA;
        int tid = threadIdx.x;
        __shared__ int cnt[3];
        if (tid < 3) cnt[tid] = 0;
        __syncthreads();
        const void* base[3] = {Am, Bm, Tm};
        #pragma unroll
        for (int m = 0; m < 3; m++) {
            bool u8 = mask_is_u8(base[m]);
            int v = mask_at(base[m], b * ABATCH + tid, u8) ? 1 : 0;
            #pragma unroll
            for (int o = 16; o > 0; o >>= 1)
                v += __shfl_down_sync(0xffffffffu, v, o);
            if ((tid & 31) == 0) atomicAdd(&cnt[m], v);
        }
        __syncthreads();
        if (tid < 3) g_len[b * 3 + tid] = cnt[tid];
    }
}

// ---------------------------------------------------------------------------
__device__ __forceinline__ void cp_async16(uint32_t smem_addr, const void* gmem,
                                           int src_bytes) {
    asm volatile("cp.async.cg.shared.global [%0], [%1], 16, %2;\n"
                 :: "r"(smem_addr), "l"(gmem), "r"(src_bytes));
}
__device__ __forceinline__ uint32_t smem_u32(const void* p) {
    uint32_t a;
    asm("{ .reg .u64 t; cvta.to.shared.u64 t, %1; cvt.u32.u64 %0, t; }" : "=r"(a) : "l"(p));
    return a;
}
__device__ __forceinline__ void mma_f16(float* c, uint32_t a0, uint32_t a1,
                                        uint32_t a2, uint32_t a3,
                                        uint32_t b0, uint32_t b1) {
    asm volatile(
        "mma.sync.aligned.m16n8k16.row.col.f32.f16.f16.f32 "
        "{%0,%1,%2,%3}, {%4,%5,%6,%7}, {%8,%9}, {%0,%1,%2,%3};"
        : "+f"(c[0]), "+f"(c[1]), "+f"(c[2]), "+f"(c[3])
        : "r"(a0), "r"(a1), "r"(a2), "r"(a3), "r"(b0), "r"(b1));
}
__device__ __forceinline__ void ldmatrix_x4(uint32_t* r, uint32_t addr) {
    asm volatile("ldmatrix.sync.aligned.m8n8.x4.shared.b16 {%0,%1,%2,%3}, [%4];"
                 : "=r"(r[0]), "=r"(r[1]), "=r"(r[2]), "=r"(r[3]) : "r"(addr));
}

__global__ __launch_bounds__(THREADS, 4)
void gemm_kernel(const float* __restrict__ Bt,
                 const void* __restrict__ tar,
                 float* __restrict__ C) {
    extern __shared__ char smem[];

    const int b  = blockIdx.z;
    const int m0 = blockIdx.y * BN;      // n-tile
    const int i0 = blockIdx.x * BM;      // i-tile (fastest -> pairs share B in L2)
    const int tid = threadIdx.x;

    const int L1 = g_len[b * 3 + 0];
    const int L2 = g_len[b * 3 + 1];
    const int L3 = g_len[b * 3 + 2];

    float* Cb = C + (size_t)b * BBATCH;
    const int kcol = m0 >> 6;            // BN=64: one head column per CTA

    // ---- tile-level liveness ----
    const int Li = min(L1, L3);
    const int Lk = min(L2, L3);
    if (i0 >= Li || kcol >= Lk) {
        float4 z = make_float4(0.f, 0.f, 0.f, 0.f);
        #pragma unroll
        for (int q = 0; q < 16; q++) {
            int c = tid + q * THREADS;              // 2048 chunks
            int row = i0 + (c >> 4);
            int col = m0 + (c & 15) * 4;
            *reinterpret_cast<float4*>(Cb + (size_t)row * MCOLS + col) = z;
        }
        return;
    }

    uint32_t as_base[2], bs_base[2];
    float* Bsf[2];
    #pragma unroll
    for (int s = 0; s < 2; s++) {
        as_base[s] = smem_u32(smem + s * A_ST_B);
        bs_base[s] = smem_u32(smem + 2 * A_ST_B + s * B_ST_B);
        Bsf[s] = reinterpret_cast<float*>(smem + 2 * A_ST_B + s * B_ST_B);
    }

    const int lane = tid & 31;
    const int w = tid >> 5;
    const int wm = w >> 1;      // 0..1 -> 64 rows
    const int wn = w & 1;       // 0..1 -> 32 cols
    const int g = lane >> 2;    // 0..7
    const int r = lane & 3;     // 0..3

    const int Kmin = min(L1, L2);
    const int T = (Kmin + BK - 1) / BK;   // 4..8

    const uint16_t* Ab = g_Ah + b * ABATCH + i0 * NDIM;
    const float* Bb = Bt + (size_t)b * BBATCH + m0;

    float acc[4][4][4];
    #pragma unroll
    for (int mf = 0; mf < 4; mf++)
        #pragma unroll
        for (int nf = 0; nf < 4; nf++)
            #pragma unroll
            for (int q = 0; q < 4; q++) acc[mf][nf][q] = 0.0f;

    // producer coords (128 threads)
    const int a_r0 = tid >> 2;       // rows tid>>2 (0..31), +32q
    const int a_c  = tid & 3;        // 8-f16 chunk (32 f16/row -> 4 chunks)
    const int b_j0 = tid >> 4;       // rows 0..7, +8q
    const int b_c  = tid & 15;       // 4-f32 chunk (64 f32/row -> 16 chunks)

    auto issue = [&](int t, int s) {
        const int k0 = t * BK;
        {
            int kk = k0 + a_c * 8;
            int nb = 2 * (Kmin - kk);
            nb = nb < 0 ? 0 : (nb > 16 ? 16 : nb);
            #pragma unroll
            for (int q = 0; q < 4; q++) {
                int row = a_r0 + q * 32;
                cp_async16(as_base[s] + (row * ASTRH + a_c * 8) * 2,
                           Ab + row * NDIM + kk, nb);
            }
        }
        #pragma unroll
        for (int q = 0; q < 4; q++) {
            int jj = b_j0 + q * 8;
            int j = k0 + jj;
            cp_async16(bs_base[s] + (jj * BSTR + b_c * 4) * 4,
                       Bb + (size_t)j * MCOLS + b_c * 4,
                       (j < Kmin) ? 16 : 0);
        }
        asm volatile("cp.async.commit_group;\n" ::: "memory");
    };

    // consumer addressing (A: verified R8; B: verified R7; strides re-audited)
    const int lm = lane & 15;
    const int lh = lane >> 4;
    const uint32_t a_off0 = ((wm * 64 + lm) * ASTRH + lh * 8) * 2;

    issue(0, 0);

    for (int t = 0; t < T; t++) {
        const int s = t & 1;
        if (t + 1 < T) {
            issue(t + 1, s ^ 1);
            asm volatile("cp.async.wait_group 1;\n" ::: "memory");
        } else {
            asm volatile("cp.async.wait_group 0;\n" ::: "memory");
        }
        __syncthreads();

        const float* Bw = &Bsf[s][(2 * r) * BSTR + wn * 32 + g];

        #pragma unroll
        for (int ks = 0; ks < 2; ks++) {
            uint32_t af[4][4];
            uint32_t b0[4], b1[4];
            #pragma unroll
            for (int mf = 0; mf < 4; mf++)
                ldmatrix_x4(af[mf], as_base[s] + a_off0
                            + (mf * 16 * ASTRH + ks * 16) * 2);
            #pragma unroll
            for (int nf = 0; nf < 4; nf++) {
                const float* p = Bw + ks * 16 * BSTR + nf * 8;
                b0[nf] = pack_h2(p[0], p[BSTR]);
                b1[nf] = pack_h2(p[8 * BSTR], p[9 * BSTR]);
            }
            #pragma unroll
            for (int mf = 0; mf < 4; mf++)
                #pragma unroll
                for (int nf = 0; nf < 4; nf++)
                    mma_f16(acc[mf][nf], af[mf][0], af[mf][1],
                            af[mf][2], af[mf][3], b0[nf], b1[nf]);
        }
        __syncthreads();
    }

    // ---- epilogue ----
    const bool u8 = mask_is_u8(tar);
    const bool vcol = (kcol < L2);

    bool rmask[4][2];
    #pragma unroll
    for (int mf = 0; mf < 4; mf++) {
        #pragma unroll
        for (int h = 0; h < 2; h++) {
            int i = i0 + wm * 64 + mf * 16 + g + h * 8;
            rmask[mf][h] = vcol && (i < L1)
                           && mask_at(tar, b * ABATCH + i * NDIM + kcol, u8);
        }
    }

    #pragma unroll
    for (int mf = 0; mf < 4; mf++) {
        int row = i0 + wm * 64 + mf * 16 + g;
        #pragma unroll
        for (int nf = 0; nf < 4; nf++) {
            int col = m0 + wn * 32 + nf * 8 + r * 2;
            float2 v0 = rmask[mf][0] ? make_float2(acc[mf][nf][0], acc[mf][nf][1])
                                     : make_float2(0.0f, 0.0f);
            float2 v1 = rmask[mf][1] ? make_float2(acc[mf][nf][2], acc[mf][nf][3])
                                     : make_float2(0.0f, 0.0f);
            *reinterpret_cast<float2*>(Cb + (size_t)row * MCOLS + col) = v0;
            *reinterpret_cast<float2*>(Cb + (size_t)(row + 8) * MCOLS + col) = v1;
        }
    }
}

// ---------------------------------------------------------------------------
extern "C" void kernel_launch(void* const* d_in, const int* in_sizes, int n_in,
                              void* d_out, int out_size) {
    (void)in_sizes; (void)n_in; (void)out_size;
    const float* A  = (const float*)d_in[0];
    const void*  Am = d_in[1];
    const float* Bt = (const float*)d_in[2];
    const void*  Bm = d_in[3];
    const void*  Tm = d_in[4];
    float* C = (float*)d_out;

    cudaFuncSetAttribute(gemm_kernel,
                         cudaFuncAttributeMaxDynamicSharedMemorySize, SMEM_BYTES);

    prep_kernel<<<NB_CONVA + BSZ, 256>>>(A, Am, Bm, Tm);

    dim3 grid(NDIM / BM, MCOLS / BN, BSZ);   // (2, 256, 16)
    gemm_kernel<<<grid, THREADS, SMEM_BYTES>>>(Bt, Tm, C);
}